// round 2
// baseline (speedup 1.0000x reference)
#include <cuda_runtime.h>
#include <math.h>

// Problem constants
#define BB 64
#define SS 256
#define DD 512

// Scratch (allocation-free rule: __device__ globals)
__device__ float g_A[BB * SS * SS];     // attention matrix A [B,S,S]
__device__ float g_F0a[BB * SS * DD];   // A^T @ W0
__device__ float g_F1a[BB * SS * DD];   // A  @ W1
__device__ float g_sq0[BB * SS];
__device__ float g_sq1[BB * SS];

// ---------------------------------------------------------------------------
// Kernel 0: masked squared row norms
// ---------------------------------------------------------------------------
__global__ __launch_bounds__(128) void sqnorm_kernel(
    const float* __restrict__ F0r, const float* __restrict__ F1r,
    const float* __restrict__ m0, const float* __restrict__ m1)
{
    int row = blockIdx.x;           // b*S + s
    int tid = threadIdx.x;          // 128 threads, one float4 each (512 elems)
    const float4* r0 = (const float4*)(F0r + (size_t)row * DD);
    const float4* r1 = (const float4*)(F1r + (size_t)row * DD);
    float4 a = r0[tid];
    float4 b = r1[tid];
    float s0 = a.x * a.x + a.y * a.y + a.z * a.z + a.w * a.w;
    float s1 = b.x * b.x + b.y * b.y + b.z * b.z + b.w * b.w;
    #pragma unroll
    for (int o = 16; o > 0; o >>= 1) {
        s0 += __shfl_xor_sync(0xFFFFFFFFu, s0, o);
        s1 += __shfl_xor_sync(0xFFFFFFFFu, s1, o);
    }
    __shared__ float sh0[4], sh1[4];
    int w = tid >> 5;
    if ((tid & 31) == 0) { sh0[w] = s0; sh1[w] = s1; }
    __syncthreads();
    if (tid == 0) {
        s0 = sh0[0] + sh0[1] + sh0[2] + sh0[3];
        s1 = sh1[0] + sh1[1] + sh1[2] + sh1[3];
        g_sq0[row] = s0 * m0[row];   // mask in {0,1}
        g_sq1[row] = s1 * m1[row];
    }
}

// ---------------------------------------------------------------------------
// GEMM1: per-batch  cross = F0 @ F1^T  (M=N=256, K=512), epilogue -> A
// 128x128 block tile, BK=8, 256 threads, 8x8 per-thread (split halves).
// ---------------------------------------------------------------------------
__global__ __launch_bounds__(256) void gemm1_kernel(
    const float* __restrict__ F0, const float* __restrict__ F1,
    const float* __restrict__ m0, const float* __restrict__ m1)
{
    __shared__ float As[2][8][128];
    __shared__ float Bs[2][8][128];

    const int b   = blockIdx.z;
    const int m0b = blockIdx.y * 128;
    const int n0b = blockIdx.x * 128;
    const float* Ag = F0 + (size_t)b * SS * DD;
    const float* Bg = F1 + (size_t)b * SS * DD;

    const int tid = threadIdx.x;
    const int tx  = tid & 15;
    const int ty  = tid >> 4;
    const int tx4 = tx * 4;
    const int ty4 = ty * 4;

    const int lr = tid >> 1;         // 0..127 (tile row)
    const int lc = (tid & 1) * 4;    // 0 or 4  (k offset)

    float acc[8][8];
    #pragma unroll
    for (int i = 0; i < 8; i++)
        #pragma unroll
        for (int j = 0; j < 8; j++) acc[i][j] = 0.f;

    // prologue
    {
        float4 av = *(const float4*)(Ag + (size_t)(m0b + lr) * DD + lc);
        float4 bv = *(const float4*)(Bg + (size_t)(n0b + lr) * DD + lc);
        As[0][lc + 0][lr] = av.x; As[0][lc + 1][lr] = av.y;
        As[0][lc + 2][lr] = av.z; As[0][lc + 3][lr] = av.w;
        Bs[0][lc + 0][lr] = bv.x; Bs[0][lc + 1][lr] = bv.y;
        Bs[0][lc + 2][lr] = bv.z; Bs[0][lc + 3][lr] = bv.w;
    }
    __syncthreads();

    int cur = 0;
    const int T = DD / 8;    // 64 k-tiles
    for (int t = 0; t < T; t++) {
        float4 an, bn;
        if (t < T - 1) {
            int kk = (t + 1) * 8;
            an = *(const float4*)(Ag + (size_t)(m0b + lr) * DD + kk + lc);
            bn = *(const float4*)(Bg + (size_t)(n0b + lr) * DD + kk + lc);
        }
        #pragma unroll
        for (int k = 0; k < 8; k++) {
            float ar[8], br[8];
            *(float4*)(ar)     = *(const float4*)(&As[cur][k][ty4]);
            *(float4*)(ar + 4) = *(const float4*)(&As[cur][k][64 + ty4]);
            *(float4*)(br)     = *(const float4*)(&Bs[cur][k][tx4]);
            *(float4*)(br + 4) = *(const float4*)(&Bs[cur][k][64 + tx4]);
            #pragma unroll
            for (int i = 0; i < 8; i++)
                #pragma unroll
                for (int j = 0; j < 8; j++)
                    acc[i][j] = fmaf(ar[i], br[j], acc[i][j]);
        }
        if (t < T - 1) {
            int nx = cur ^ 1;
            As[nx][lc + 0][lr] = an.x; As[nx][lc + 1][lr] = an.y;
            As[nx][lc + 2][lr] = an.z; As[nx][lc + 3][lr] = an.w;
            Bs[nx][lc + 0][lr] = bn.x; Bs[nx][lc + 1][lr] = bn.y;
            Bs[nx][lc + 2][lr] = bn.z; Bs[nx][lc + 3][lr] = bn.w;
            __syncthreads();
            cur = nx;
        }
    }

    // epilogue: A = 1/(1+sqrt(max(sq0+sq1-2*m0*m1*cross,0)))
    float sq0r[8], m0r[8], sq1c[8], m1c[8];
    int rows[8], cols[8];
    #pragma unroll
    for (int i = 0; i < 8; i++) {
        rows[i] = (i < 4) ? (ty4 + i) : (64 + ty4 + i - 4);
        cols[i] = (i < 4) ? (tx4 + i) : (64 + tx4 + i - 4);
        sq0r[i] = g_sq0[b * SS + m0b + rows[i]];
        m0r[i]  = m0[b * SS + m0b + rows[i]];
        sq1c[i] = g_sq1[b * SS + n0b + cols[i]];
        m1c[i]  = m1[b * SS + n0b + cols[i]];
    }
    float* Aout = g_A + (size_t)b * SS * SS;
    #pragma unroll
    for (int i = 0; i < 8; i++) {
        float v[8];
        #pragma unroll
        for (int j = 0; j < 8; j++) {
            float d2 = sq0r[i] + sq1c[j] - 2.f * m0r[i] * m1c[j] * acc[i][j];
            d2 = fmaxf(d2, 0.f);
            float nrm = sqrtf(d2);
            v[j] = 1.f / (1.f + nrm);
        }
        size_t base = (size_t)(m0b + rows[i]) * SS + n0b;
        *(float4*)&Aout[base + tx4]      = make_float4(v[0], v[1], v[2], v[3]);
        *(float4*)&Aout[base + 64 + tx4] = make_float4(v[4], v[5], v[6], v[7]);
    }
}

// ---------------------------------------------------------------------------
// GEMM2: MODE=0:  F0a[j,d] = sum_i A[i,j] * W0[i,d]   (A read [k][m] direct)
//        MODE=1:  F1a[i,d] = sum_j A[i,j] * W1[j,d]   (A read transposed)
// M=256, N=512, K=256 per batch.
// ---------------------------------------------------------------------------
template <int MODE>
__global__ __launch_bounds__(256) void gemm2_kernel(const float* __restrict__ Wmat)
{
    __shared__ float As[2][8][128];
    __shared__ float Bs[2][8][128];

    const int b   = blockIdx.z;
    const int m0b = blockIdx.y * 128;   // over S
    const int n0b = blockIdx.x * 128;   // over D
    const float* Ag = g_A + (size_t)b * SS * SS;

    const int tid = threadIdx.x;
    const int tx  = tid & 15;
    const int ty  = tid >> 4;
    const int tx4 = tx * 4;
    const int ty4 = ty * 4;

    const int lr  = tid >> 1;          // transposed-load indices
    const int lc  = (tid & 1) * 4;
    const int dr  = tid >> 5;          // direct-load indices (8 rows x 32 f4)
    const int dc  = (tid & 31) * 4;

    float acc[8][8];
    #pragma unroll
    for (int i = 0; i < 8; i++)
        #pragma unroll
        for (int j = 0; j < 8; j++) acc[i][j] = 0.f;

    // prologue (k-tile 0)
    {
        if (MODE == 0) {
            float4 av = *(const float4*)(Ag + (size_t)dr * SS + m0b + dc);
            *(float4*)&As[0][dr][dc] = av;
        } else {
            float4 av = *(const float4*)(Ag + (size_t)(m0b + lr) * SS + lc);
            As[0][lc + 0][lr] = av.x; As[0][lc + 1][lr] = av.y;
            As[0][lc + 2][lr] = av.z; As[0][lc + 3][lr] = av.w;
        }
        float4 bv = *(const float4*)(Wmat + (size_t)dr * DD + n0b + dc);
        *(float4*)&Bs[0][dr][dc] = bv;
    }
    __syncthreads();

    int cur = 0;
    const int T = SS / 8;    // 32 k-tiles
    for (int t = 0; t < T; t++) {
        float4 an, bn;
        if (t < T - 1) {
            int kk = (t + 1) * 8;
            if (MODE == 0)
                an = *(const float4*)(Ag + (size_t)(kk + dr) * SS + m0b + dc);
            else
                an = *(const float4*)(Ag + (size_t)(m0b + lr) * SS + kk + lc);
            bn = *(const float4*)(Wmat + (size_t)(kk + dr) * DD + n0b + dc);
        }
        #pragma unroll
        for (int k = 0; k < 8; k++) {
            float ar[8], br[8];
            *(float4*)(ar)     = *(const float4*)(&As[cur][k][ty4]);
            *(float4*)(ar + 4) = *(const float4*)(&As[cur][k][64 + ty4]);
            *(float4*)(br)     = *(const float4*)(&Bs[cur][k][tx4]);
            *(float4*)(br + 4) = *(const float4*)(&Bs[cur][k][64 + tx4]);
            #pragma unroll
            for (int i = 0; i < 8; i++)
                #pragma unroll
                for (int j = 0; j < 8; j++)
                    acc[i][j] = fmaf(ar[i], br[j], acc[i][j]);
        }
        if (t < T - 1) {
            int nx = cur ^ 1;
            if (MODE == 0) {
                *(float4*)&As[nx][dr][dc] = an;
            } else {
                As[nx][lc + 0][lr] = an.x; As[nx][lc + 1][lr] = an.y;
                As[nx][lc + 2][lr] = an.z; As[nx][lc + 3][lr] = an.w;
            }
            *(float4*)&Bs[nx][dr][dc] = bn;
            __syncthreads();
            cur = nx;
        }
    }

    float* Cout = (MODE == 0 ? g_F0a : g_F1a) + (size_t)b * SS * DD;
    #pragma unroll
    for (int i = 0; i < 8; i++) {
        int rr = (i < 4) ? (ty4 + i) : (64 + ty4 + i - 4);
        size_t base = (size_t)(m0b + rr) * DD + n0b;
        *(float4*)&Cout[base + tx4]      = make_float4(acc[i][0], acc[i][1], acc[i][2], acc[i][3]);
        *(float4*)&Cout[base + 64 + tx4] = make_float4(acc[i][4], acc[i][5], acc[i][6], acc[i][7]);
    }
}

// ---------------------------------------------------------------------------
// Conv (2ch, height 3, pad 2) + bias + tanh + avgpool(3) fused.
// ---------------------------------------------------------------------------
__device__ __forceinline__ float fast_tanh(float x)
{
    float e = __expf(2.f * x);
    return 1.f - __fdividef(2.f, 1.f + e);
}

__global__ __launch_bounds__(256) void conv_kernel(
    const float* __restrict__ F0r, const float* __restrict__ F1r,
    const float* __restrict__ m0, const float* __restrict__ m1,
    const float* __restrict__ conv_w, const float* __restrict__ conv_b,
    float* __restrict__ out)
{
    const int p = blockIdx.z & 1;       // 0 -> out0, 1 -> out1
    const int b = blockIdx.z >> 1;
    const float* F  = p ? F1r : F0r;
    const float* mk = p ? m1 : m0;
    const float* Fa = p ? g_F1a : g_F0a;
    float* o = out + ((size_t)p * BB + b) * SS * DD;

    const int s = blockIdx.y;
    const int d = blockIdx.x * 256 + threadIdx.x;

    float w0[3], w1[3];
    #pragma unroll
    for (int h = 0; h < 3; h++) { w0[h] = conv_w[h]; w1[h] = conv_w[3 + h]; }
    const float cb = conv_b[0];

    float lF[5], lA[5];
    #pragma unroll
    for (int u = 0; u < 5; u++) {
        int t = s - 2 + u;
        bool in = (t >= 0) && (t < SS);
        lF[u] = in ? F[((size_t)b * SS + t) * DD + d] * mk[b * SS + t] : 0.f;
        lA[u] = in ? Fa[((size_t)b * SS + t) * DD + d] : 0.f;
    }
    float acc = 0.f;
    #pragma unroll
    for (int u = 0; u < 3; u++) {
        float y = cb;
        #pragma unroll
        for (int h = 0; h < 3; h++)
            y += w0[h] * lF[u + h] + w1[h] * lA[u + h];
        acc += fast_tanh(y);
    }
    o[(size_t)s * DD + d] = acc * (1.f / 3.f);
}

// ---------------------------------------------------------------------------
// Launch
// ---------------------------------------------------------------------------
extern "C" void kernel_launch(void* const* d_in, const int* in_sizes, int n_in,
                              void* d_out, int out_size)
{
    const float* F0r    = (const float*)d_in[0];
    const float* F1r    = (const float*)d_in[1];
    const float* m0     = (const float*)d_in[2];
    const float* m1     = (const float*)d_in[3];
    const float* W0     = (const float*)d_in[4];
    const float* W1     = (const float*)d_in[5];
    const float* conv_w = (const float*)d_in[6];
    const float* conv_b = (const float*)d_in[7];
    float* out = (float*)d_out;

    sqnorm_kernel<<<BB * SS, 128>>>(F0r, F1r, m0, m1);

    dim3 g1(SS / 128, SS / 128, BB);     // 2 x 2 x 64
    gemm1_kernel<<<g1, 256>>>(F0r, F1r, m0, m1);

    dim3 g2(DD / 128, SS / 128, BB);     // 4 x 2 x 64
    gemm2_kernel<0><<<g2, 256>>>(W0);
    gemm2_kernel<1><<<g2, 256>>>(W1);

    dim3 gc(DD / 256, SS, 2 * BB);       // 2 x 256 x 128
    conv_kernel<<<gc, 256>>>(F0r, F1r, m0, m1, conv_w, conv_b, out);
}

// round 5
// speedup vs baseline: 1.6906x; 1.6906x over previous
#include <cuda_runtime.h>
#include <cstdint>
#include <math.h>

#define BB 64
#define SS 256
#define DD 512

// ---------------- scratch (__device__ globals; no allocation) ---------------
__device__ float g_A  [BB * SS * SS];    // A[b][i][j]   (tf32-rounded)
__device__ float g_At [BB * SS * SS];    // A[b][j][i]   (tf32-rounded)
__device__ float g_F0a[BB * SS * DD];
__device__ float g_F1a[BB * SS * DD];
__device__ float g_W0t[DD * SS];         // W0^T [d][k]  (tf32-rounded)
__device__ float g_W1t[DD * SS];
__device__ float g_sq0[BB * SS];
__device__ float g_sq1[BB * SS];

// ---------------- helpers ---------------------------------------------------
__device__ __forceinline__ uint32_t smem_u32(const void* p) {
    uint32_t a;
    asm("{ .reg .u64 t; cvta.to.shared.u64 t, %1; cvt.u32.u64 %0, t; }" : "=r"(a) : "l"(p));
    return a;
}
__device__ __forceinline__ float rtf32(float x) {   // round-to-nearest tf32
    uint32_t u;
    asm("cvt.rna.tf32.f32 %0, %1;" : "=r"(u) : "f"(x));
    return __uint_as_float(u);
}
__device__ __forceinline__ uint32_t lds32(uint32_t a) {
    uint32_t v;
    asm volatile("ld.shared.b32 %0, [%1];" : "=r"(v) : "r"(a));
    return v;
}
#define CP_ASYNC16(dst, src) \
    asm volatile("cp.async.cg.shared.global [%0], [%1], 16;" :: "r"(dst), "l"(src))
#define CP_COMMIT() asm volatile("cp.async.commit_group;" ::: "memory")
#define CP_WAIT1()  asm volatile("cp.async.wait_group 1;" ::: "memory")

__device__ __forceinline__ void mma_tf32(float* c, const uint32_t* a, const uint32_t* b) {
    asm volatile(
        "mma.sync.aligned.m16n8k8.row.col.f32.tf32.tf32.f32 "
        "{%0,%1,%2,%3}, {%4,%5,%6,%7}, {%8,%9}, {%0,%1,%2,%3};"
        : "+f"(c[0]), "+f"(c[1]), "+f"(c[2]), "+f"(c[3])
        : "r"(a[0]), "r"(a[1]), "r"(a[2]), "r"(a[3]), "r"(b[0]), "r"(b[1]));
}

// ---------------------------------------------------------------------------
// Kernel 0: masked squared row norms
// ---------------------------------------------------------------------------
__global__ __launch_bounds__(128) void sqnorm_kernel(
    const float* __restrict__ F0r, const float* __restrict__ F1r,
    const float* __restrict__ m0, const float* __restrict__ m1)
{
    int row = blockIdx.x;
    int tid = threadIdx.x;
    const float4* r0 = (const float4*)(F0r + (size_t)row * DD);
    const float4* r1 = (const float4*)(F1r + (size_t)row * DD);
    float4 a = r0[tid];
    float4 b = r1[tid];
    float s0 = a.x * a.x + a.y * a.y + a.z * a.z + a.w * a.w;
    float s1 = b.x * b.x + b.y * b.y + b.z * b.z + b.w * b.w;
    #pragma unroll
    for (int o = 16; o > 0; o >>= 1) {
        s0 += __shfl_xor_sync(0xFFFFFFFFu, s0, o);
        s1 += __shfl_xor_sync(0xFFFFFFFFu, s1, o);
    }
    __shared__ float sh0[4], sh1[4];
    int w = tid >> 5;
    if ((tid & 31) == 0) { sh0[w] = s0; sh1[w] = s1; }
    __syncthreads();
    if (tid == 0) {
        s0 = sh0[0] + sh0[1] + sh0[2] + sh0[3];
        s1 = sh1[0] + sh1[1] + sh1[2] + sh1[3];
        g_sq0[row] = s0 * m0[row];
        g_sq1[row] = s1 * m1[row];
    }
}

// ---------------------------------------------------------------------------
// Kernel 1: W transpose + tf32 rounding.  W [256,512] -> Wt [512,256]
// ---------------------------------------------------------------------------
__global__ __launch_bounds__(256) void wtrans_kernel(
    const float* __restrict__ W0, const float* __restrict__ W1)
{
    __shared__ float t[32][33];
    int sel = blockIdx.z;
    const float* W = sel ? W1 : W0;
    float* Wt = sel ? g_W1t : g_W0t;
    int d0 = blockIdx.x * 32, k0 = blockIdx.y * 32;
    int tx = threadIdx.x, ty = threadIdx.y;           // 32 x 8
    #pragma unroll
    for (int r = 0; r < 32; r += 8)
        t[ty + r][tx] = W[(size_t)(k0 + ty + r) * DD + d0 + tx];
    __syncthreads();
    #pragma unroll
    for (int r = 0; r < 32; r += 8)
        Wt[(size_t)(d0 + ty + r) * SS + k0 + tx] = rtf32(t[tx][ty + r]);
}

// ---------------------------------------------------------------------------
// Unified mma.sync tf32 GEMM.  Block tile 128x128, 8 warps (64x32 each), BK=16.
// Both operands in smem as [row][16k] padded to 20 floats (80 B/row).
// MODE 0: cross = F0 @ F1^T (K=512) -> attention epilogue -> g_A, g_At
// MODE 1: F0a = At-rows @ W0t-rows (K=256) -> g_F0a
// MODE 2: F1a = A-rows  @ W1t-rows (K=256) -> g_F1a
// ---------------------------------------------------------------------------
#define ROWPAD 20                 // floats per smem row (16 + 4 pad)
#define OPER_BYTES (128 * ROWPAD * 4)      // 10240
#define STAGE_BYTES (2 * OPER_BYTES)       // 20480
#define GEMM_SMEM (2 * STAGE_BYTES)        // 40960 (< 48KB default)

template <int MODE>
__global__ __launch_bounds__(256, 2) void gemm_tc(
    const float* __restrict__ F0r, const float* __restrict__ F1r,
    const float* __restrict__ m0_, const float* __restrict__ m1_)
{
    extern __shared__ char smem[];
    constexpr int KTOT = (MODE == 0) ? 512 : 256;
    constexpr int T    = KTOT / 16;
    constexpr int LDK  = (MODE == 0) ? 512 : 256;

    const int tid = threadIdx.x;
    const int wid = tid >> 5, lane = tid & 31;
    const int g = lane >> 2, t4 = lane & 3;
    const int wm = wid & 1, wn = wid >> 1;     // 2 x 4 warp grid
    const int b = blockIdx.z, mt = blockIdx.y, nt = blockIdx.x;

    uint32_t sb = smem_u32(smem);

    const float* Ag;
    const float* Bg;
    if (MODE == 0) {
        Ag = F0r + (size_t)b * SS * DD + (size_t)mt * 128 * DD;
        Bg = F1r + (size_t)b * SS * DD + (size_t)nt * 128 * DD;
    } else if (MODE == 1) {
        Ag = g_At + (size_t)b * SS * SS + (size_t)mt * 128 * SS;
        Bg = g_W0t + (size_t)nt * 128 * SS;
    } else {
        Ag = g_A + (size_t)b * SS * SS + (size_t)mt * 128 * SS;
        Bg = g_W1t + (size_t)nt * 128 * SS;
    }

    float acc[4][4][4];
    #pragma unroll
    for (int i = 0; i < 4; i++)
        #pragma unroll
        for (int j = 0; j < 4; j++)
            #pragma unroll
            for (int r = 0; r < 4; r++) acc[i][j][r] = 0.f;

    // loader: 1024 16B chunks per stage (A 512 + B 512), 4 per thread
    const int lrow = tid >> 2;            // 0..63 base row for chunk pair
    const int lpart = tid & 3;            // 16B part within 64B row
    auto load_tile = [&](int t, int s) {
        uint32_t ab = sb + s * STAGE_BYTES;
        uint32_t bb = ab + OPER_BYTES;
        int k0 = t * 16;
        #pragma unroll
        for (int r = 0; r < 2; r++) {
            int row = lrow + r * 64;
            uint32_t doff = (uint32_t)(row * 80 + lpart * 16);
            const float* sa = Ag + (size_t)row * LDK + k0 + lpart * 4;
            const float* sbp = Bg + (size_t)row * LDK + k0 + lpart * 4;
            CP_ASYNC16(ab + doff, sa);
            CP_ASYNC16(bb + doff, sbp);
        }
    };

    load_tile(0, 0); CP_COMMIT();
    load_tile(1, 1); CP_COMMIT();

    const uint32_t aoff = (uint32_t)((wm * 64 + g) * 80 + t4 * 4);
    const uint32_t boff = (uint32_t)((wn * 32 + g) * 80 + t4 * 4);

    for (int t = 0; t < T; t++) {
        int s = t & 1;
        CP_WAIT1();
        __syncthreads();
        uint32_t ab = sb + s * STAGE_BYTES + aoff;
        uint32_t bb = sb + s * STAGE_BYTES + OPER_BYTES + boff;
        #pragma unroll
        for (int ks = 0; ks < 2; ks++) {
            uint32_t af[4][4], bf[4][2];
            #pragma unroll
            for (int mf = 0; mf < 4; mf++) {
                uint32_t base = ab + mf * 1280 + ks * 32;
                af[mf][0] = lds32(base);
                af[mf][1] = lds32(base + 640);
                af[mf][2] = lds32(base + 16);
                af[mf][3] = lds32(base + 656);
            }
            #pragma unroll
            for (int nf = 0; nf < 4; nf++) {
                uint32_t base = bb + nf * 640 + ks * 32;
                bf[nf][0] = lds32(base);
                bf[nf][1] = lds32(base + 16);
            }
            #pragma unroll
            for (int mf = 0; mf < 4; mf++)
                #pragma unroll
                for (int nf = 0; nf < 4; nf++)
                    mma_tf32(acc[mf][nf], af[mf], bf[nf]);
        }
        __syncthreads();
        if (t + 2 < T) load_tile(t + 2, s);
        CP_COMMIT();
    }

    // -------------------- epilogue --------------------
    if (MODE != 0) {
        float* O = ((MODE == 1) ? g_F0a : g_F1a) + (size_t)b * SS * DD;
        #pragma unroll
        for (int mf = 0; mf < 4; mf++) {
            int m = mt * 128 + wm * 64 + mf * 16 + g;
            #pragma unroll
            for (int nf = 0; nf < 4; nf++) {
                int col = nt * 128 + wn * 32 + nf * 8 + 2 * t4;
                *(float2*)&O[(size_t)m * DD + col] =
                    make_float2(acc[mf][nf][0], acc[mf][nf][1]);
                *(float2*)&O[(size_t)(m + 8) * DD + col] =
                    make_float2(acc[mf][nf][2], acc[mf][nf][3]);
            }
        }
        return;
    }

    // MODE 0: attention epilogue via smem staging (two 64-row halves)
    float* tile = (float*)smem;                         // [64][132]
    float* s_sq0 = (float*)(smem + 33792);              // [128]
    float* s_a0  = s_sq0 + 128;                         // [128] = 2*m0
    float* s_sq1 = s_a0 + 128;                          // [128]
    float* s_m1  = s_sq1 + 128;                         // [128]

    __syncthreads();   // all mma smem reads done (stages now dead)
    if (tid < 128) {
        int i = tid;
        s_sq0[i] = g_sq0[b * SS + mt * 128 + i];
        s_a0[i]  = 2.f * m0_[b * SS + mt * 128 + i];
        s_sq1[i] = g_sq1[b * SS + nt * 128 + i];
        s_m1[i]  = m1_[b * SS + nt * 128 + i];
    }

    float* Aout  = g_A  + (size_t)b * SS * SS;
    float* Atout = g_At + (size_t)b * SS * SS;

    #pragma unroll 1
    for (int h = 0; h < 2; h++) {
        __syncthreads();
        if (wm == h) {
            #pragma unroll
            for (int mf = 0; mf < 4; mf++) {
                int lr = mf * 16 + g;
                #pragma unroll
                for (int nf = 0; nf < 4; nf++) {
                    int col = wn * 32 + nf * 8 + 2 * t4;
                    *(float2*)&tile[lr * 132 + col] =
                        make_float2(acc[mf][nf][0], acc[mf][nf][1]);
                    *(float2*)&tile[(lr + 8) * 132 + col] =
                        make_float2(acc[mf][nf][2], acc[mf][nf][3]);
                }
            }
        }
        __syncthreads();

        // pass 1: A row-major, float4 per thread iter
        #pragma unroll
        for (int it = 0; it < 8; it++) {
            int lin = it * 1024 + tid * 4;       // over 64*128 elems
            int row = lin >> 7, col = lin & 127;
            int grow = h * 64 + row;
            float s0v = s_sq0[grow], a0v = s_a0[grow];
            float4 cr = *(float4*)&tile[row * 132 + col];
            float v0, v1, v2, v3;
            {
                float d2 = fmaxf(s0v + s_sq1[col]     - a0v * s_m1[col]     * cr.x, 0.f);
                v0 = rtf32(1.f / (1.f + sqrtf(d2)));
                d2 = fmaxf(s0v + s_sq1[col + 1] - a0v * s_m1[col + 1] * cr.y, 0.f);
                v1 = rtf32(1.f / (1.f + sqrtf(d2)));
                d2 = fmaxf(s0v + s_sq1[col + 2] - a0v * s_m1[col + 2] * cr.z, 0.f);
                v2 = rtf32(1.f / (1.f + sqrtf(d2)));
                d2 = fmaxf(s0v + s_sq1[col + 3] - a0v * s_m1[col + 3] * cr.w, 0.f);
                v3 = rtf32(1.f / (1.f + sqrtf(d2)));
            }
            *(float4*)&Aout[(size_t)(mt * 128 + grow) * SS + nt * 128 + col] =
                make_float4(v0, v1, v2, v3);
        }

        // pass 2: At (transposed), 4 rows per thread iter
        #pragma unroll
        for (int it = 0; it < 8; it++) {
            int pair = it * 256 + tid;           // over 128 cols * 16 rowgroups
            int col = pair >> 4, rg = pair & 15;
            int r0 = rg * 4;
            float s1v = s_sq1[col], m1v = s_m1[col];
            float v[4];
            #pragma unroll
            for (int q = 0; q < 4; q++) {
                int row = r0 + q, grow = h * 64 + row;
                float cr = tile[row * 132 + col];
                float d2 = fmaxf(s_sq0[grow] + s1v - s_a0[grow] * m1v * cr, 0.f);
                v[q] = rtf32(1.f / (1.f + sqrtf(d2)));
            }
            *(float4*)&Atout[(size_t)(nt * 128 + col) * SS + mt * 128 + h * 64 + r0] =
                make_float4(v[0], v[1], v[2], v[3]);
        }
    }
}

// ---------------------------------------------------------------------------
// Conv (2ch, h=3, pad 2) + bias + tanh + avgpool(3), 8-row segments per thread
// ---------------------------------------------------------------------------
__device__ __forceinline__ float fast_tanh(float x)
{
    float e = __expf(2.f * x);
    return 1.f - __fdividef(2.f, 1.f + e);
}

__global__ __launch_bounds__(256) void conv_kernel(
    const float* __restrict__ F0r, const float* __restrict__ F1r,
    const float* __restrict__ m0, const float* __restrict__ m1,
    const float* __restrict__ conv_w, const float* __restrict__ conv_b,
    float* __restrict__ out)
{
    const int p = blockIdx.z & 1;
    const int b = blockIdx.z >> 1;
    const float* F  = p ? F1r : F0r;
    const float* mk = p ? m1 : m0;
    const float* Fa = p ? g_F1a : g_F0a;
    float* o = out + ((size_t)p * BB + b) * SS * DD;

    const int s0 = blockIdx.y * 8;
    const int d  = blockIdx.x * 256 + threadIdx.x;

    float w0[3], w1[3];
    #pragma unroll
    for (int h = 0; h < 3; h++) { w0[h] = conv_w[h]; w1[h] = conv_w[3 + h]; }
    const float cb = conv_b[0];

    float xf[12], xa[12];
    #pragma unroll
    for (int u = 0; u < 12; u++) {
        int t = s0 - 2 + u;
        bool in = (t >= 0) && (t < SS);
        if (in) {
            float mv = mk[b * SS + t];
            xf[u] = F [((size_t)b * SS + t) * DD + d] * mv;
            xa[u] = Fa[((size_t)b * SS + t) * DD + d];
        } else { xf[u] = 0.f; xa[u] = 0.f; }
    }

    float y[10];
    #pragma unroll
    for (int u = 0; u < 10; u++) {
        float acc = cb;
        #pragma unroll
        for (int h = 0; h < 3; h++)
            acc += w0[h] * xf[u + h] + w1[h] * xa[u + h];
        y[u] = fast_tanh(acc);
    }
    #pragma unroll
    for (int q = 0; q < 8; q++)
        o[(size_t)(s0 + q) * DD + d] = (y[q] + y[q + 1] + y[q + 2]) * (1.f / 3.f);
}

// ---------------------------------------------------------------------------
// Launch
// ---------------------------------------------------------------------------
extern "C" void kernel_launch(void* const* d_in, const int* in_sizes, int n_in,
                              void* d_out, int out_size)
{
    const float* F0r    = (const float*)d_in[0];
    const float* F1r    = (const float*)d_in[1];
    const float* m0     = (const float*)d_in[2];
    const float* m1     = (const float*)d_in[3];
    const float* W0     = (const float*)d_in[4];
    const float* W1     = (const float*)d_in[5];
    const float* conv_w = (const float*)d_in[6];
    const float* conv_b = (const float*)d_in[7];
    float* out = (float*)d_out;

    sqnorm_kernel<<<BB * SS, 128>>>(F0r, F1r, m0, m1);
    wtrans_kernel<<<dim3(16, 8, 2), dim3(32, 8)>>>(W0, W1);

    gemm_tc<0><<<dim3(2, 2, BB), 256, GEMM_SMEM>>>(F0r, F1r, m0, m1);
    gemm_tc<1><<<dim3(4, 2, BB), 256, GEMM_SMEM>>>(F0r, F1r, m0, m1);
    gemm_tc<2><<<dim3(4, 2, BB), 256, GEMM_SMEM>>>(F0r, F1r, m0, m1);

    conv_kernel<<<dim3(2, 32, 2 * BB), 256>>>(F0r, F1r, m0, m1, conv_w, conv_b, out);
}

// round 6
// speedup vs baseline: 2.5659x; 1.5177x over previous
#include <cuda_runtime.h>
#include <cstdint>
#include <math.h>

#define BB 64
#define SS 256
#define DD 512

// ---------------- scratch (__device__ globals; no allocation) ---------------
__device__ float g_A  [BB * SS * SS];    // A[b][i][j]   (tf32-rounded)
__device__ float g_At [BB * SS * SS];    // A[b][j][i]   (tf32-rounded)
__device__ float g_F0a[BB * SS * DD];
__device__ float g_F1a[BB * SS * DD];
__device__ float g_W0t[DD * SS];         // W0^T [d][k]  (tf32-rounded)
__device__ float g_W1t[DD * SS];
__device__ float g_sq0[BB * SS];
__device__ float g_sq1[BB * SS];

// ---------------- helpers ---------------------------------------------------
__device__ __forceinline__ uint32_t smem_u32(const void* p) {
    uint32_t a;
    asm("{ .reg .u64 t; cvta.to.shared.u64 t, %1; cvt.u32.u64 %0, t; }" : "=r"(a) : "l"(p));
    return a;
}
__device__ __forceinline__ float rtf32(float x) {   // round-to-nearest tf32
    uint32_t u;
    asm("cvt.rna.tf32.f32 %0, %1;" : "=r"(u) : "f"(x));
    return __uint_as_float(u);
}
__device__ __forceinline__ uint32_t lds32(uint32_t a) {
    uint32_t v;
    asm volatile("ld.shared.b32 %0, [%1];" : "=r"(v) : "r"(a));
    return v;
}
#define CP_ASYNC16(dst, src) \
    asm volatile("cp.async.cg.shared.global [%0], [%1], 16;" :: "r"(dst), "l"(src))
#define CP_COMMIT() asm volatile("cp.async.commit_group;" ::: "memory")
#define CP_WAIT1()  asm volatile("cp.async.wait_group 1;" ::: "memory")

__device__ __forceinline__ void mma_tf32(float* c, const uint32_t* a, const uint32_t* b) {
    asm volatile(
        "mma.sync.aligned.m16n8k8.row.col.f32.tf32.tf32.f32 "
        "{%0,%1,%2,%3}, {%4,%5,%6,%7}, {%8,%9}, {%0,%1,%2,%3};"
        : "+f"(c[0]), "+f"(c[1]), "+f"(c[2]), "+f"(c[3])
        : "r"(a[0]), "r"(a[1]), "r"(a[2]), "r"(a[3]), "r"(b[0]), "r"(b[1]));
}

// ---------------------------------------------------------------------------
// Kernel 0: masked squared row norms
// ---------------------------------------------------------------------------
__global__ __launch_bounds__(128) void sqnorm_kernel(
    const float* __restrict__ F0r, const float* __restrict__ F1r,
    const float* __restrict__ m0, const float* __restrict__ m1)
{
    int row = blockIdx.x;
    int tid = threadIdx.x;
    const float4* r0 = (const float4*)(F0r + (size_t)row * DD);
    const float4* r1 = (const float4*)(F1r + (size_t)row * DD);
    float4 a = r0[tid];
    float4 b = r1[tid];
    float s0 = a.x * a.x + a.y * a.y + a.z * a.z + a.w * a.w;
    float s1 = b.x * b.x + b.y * b.y + b.z * b.z + b.w * b.w;
    #pragma unroll
    for (int o = 16; o > 0; o >>= 1) {
        s0 += __shfl_xor_sync(0xFFFFFFFFu, s0, o);
        s1 += __shfl_xor_sync(0xFFFFFFFFu, s1, o);
    }
    __shared__ float sh0[4], sh1[4];
    int w = tid >> 5;
    if ((tid & 31) == 0) { sh0[w] = s0; sh1[w] = s1; }
    __syncthreads();
    if (tid == 0) {
        s0 = sh0[0] + sh0[1] + sh0[2] + sh0[3];
        s1 = sh1[0] + sh1[1] + sh1[2] + sh1[3];
        g_sq0[row] = s0 * m0[row];
        g_sq1[row] = s1 * m1[row];
    }
}

// ---------------------------------------------------------------------------
// Kernel 1: W transpose + tf32 rounding.  W [256,512] -> Wt [512,256]
// ---------------------------------------------------------------------------
__global__ __launch_bounds__(256) void wtrans_kernel(
    const float* __restrict__ W0, const float* __restrict__ W1)
{
    __shared__ float t[32][33];
    int sel = blockIdx.z;
    const float* W = sel ? W1 : W0;
    float* Wt = sel ? g_W1t : g_W0t;
    int d0 = blockIdx.x * 32, k0 = blockIdx.y * 32;
    int tx = threadIdx.x, ty = threadIdx.y;           // 32 x 8
    #pragma unroll
    for (int r = 0; r < 32; r += 8)
        t[ty + r][tx] = W[(size_t)(k0 + ty + r) * DD + d0 + tx];
    __syncthreads();
    #pragma unroll
    for (int r = 0; r < 32; r += 8)
        Wt[(size_t)(d0 + ty + r) * SS + k0 + tx] = rtf32(t[tx][ty + r]);
}

// ---------------------------------------------------------------------------
// mma.sync tf32 GEMM core.  Block tile 128x128, 8 warps (64x32 each), BK=16.
// smem row layout: 16 floats + 4 pad (80 B).  3-stage cp.async ring, single
// __syncthreads per mainloop iteration, loads issued 2 tiles ahead.
// ---------------------------------------------------------------------------
#define ROWPAD 20
#define OPER_BYTES (128 * ROWPAD * 4)      // 10240
#define STAGE_BYTES (2 * OPER_BYTES)       // 20480
#define NSTAGE 3
#define GEMM_SMEM (NSTAGE * STAGE_BYTES)   // 61440

// core mainloop: accumulates Ag(128 x KTOT) @ Bg(128 x KTOT)^T into acc
template <int KTOT>
__device__ __forceinline__ void gemm_mainloop(
    const float* __restrict__ Ag, const float* __restrict__ Bg,
    uint32_t sb, int tid, float acc[4][4][4],
    uint32_t aoff, uint32_t boff)
{
    constexpr int T = KTOT / 16;
    const int lrow = tid >> 2;
    const int lpart = tid & 3;

    auto load_tile = [&](int t, int s) {
        uint32_t ab = sb + s * STAGE_BYTES;
        uint32_t bb = ab + OPER_BYTES;
        int k0 = t * 16;
        #pragma unroll
        for (int r = 0; r < 2; r++) {
            int row = lrow + r * 64;
            uint32_t doff = (uint32_t)(row * 80 + lpart * 16);
            CP_ASYNC16(ab + doff, Ag + (size_t)row * KTOT + k0 + lpart * 4);
            CP_ASYNC16(bb + doff, Bg + (size_t)row * KTOT + k0 + lpart * 4);
        }
    };

    load_tile(0, 0); CP_COMMIT();
    load_tile(1, 1); CP_COMMIT();

    int s = 0;
    for (int t = 0; t < T; t++) {
        CP_WAIT1();           // tile t resident (tile t+1 may be in flight)
        __syncthreads();      // visibility of tile t; slot for t+2 is free
        int lt = t + 2;
        int ls = s + 2; if (ls >= NSTAGE) ls -= NSTAGE;
        if (lt < T) load_tile(lt, ls);
        CP_COMMIT();

        uint32_t ab = sb + s * STAGE_BYTES + aoff;
        uint32_t bb = sb + s * STAGE_BYTES + OPER_BYTES + boff;
        #pragma unroll
        for (int ks = 0; ks < 2; ks++) {
            uint32_t af[4][4], bf[4][2];
            #pragma unroll
            for (int mf = 0; mf < 4; mf++) {
                uint32_t base = ab + mf * 1280 + ks * 32;
                af[mf][0] = lds32(base);
                af[mf][1] = lds32(base + 640);
                af[mf][2] = lds32(base + 16);
                af[mf][3] = lds32(base + 656);
            }
            #pragma unroll
            for (int nf = 0; nf < 4; nf++) {
                uint32_t base = bb + nf * 640 + ks * 32;
                bf[nf][0] = lds32(base);
                bf[nf][1] = lds32(base + 16);
            }
            #pragma unroll
            for (int mf = 0; mf < 4; mf++)
                #pragma unroll
                for (int nf = 0; nf < 4; nf++)
                    mma_tf32(acc[mf][nf], af[mf], bf[nf]);
        }
        if (++s >= NSTAGE) s -= NSTAGE;
    }
}

// ---------------------------------------------------------------------------
// GEMM A (attention): cross = F0 @ F1^T (K=512) -> epilogue -> g_A, g_At
// ---------------------------------------------------------------------------
__global__ __launch_bounds__(256, 2) void gemm_attn(
    const float* __restrict__ F0r, const float* __restrict__ F1r,
    const float* __restrict__ m0_, const float* __restrict__ m1_)
{
    extern __shared__ char smem[];
    const int tid = threadIdx.x;
    const int wid = tid >> 5, lane = tid & 31;
    const int g = lane >> 2, t4 = lane & 3;
    const int wm = wid & 1, wn = wid >> 1;
    const int b = blockIdx.z, mt = blockIdx.y, nt = blockIdx.x;

    uint32_t sb = smem_u32(smem);
    const float* Ag = F0r + (size_t)b * SS * DD + (size_t)mt * 128 * DD;
    const float* Bg = F1r + (size_t)b * SS * DD + (size_t)nt * 128 * DD;

    float acc[4][4][4];
    #pragma unroll
    for (int i = 0; i < 4; i++)
        #pragma unroll
        for (int j = 0; j < 4; j++)
            #pragma unroll
            for (int r = 0; r < 4; r++) acc[i][j][r] = 0.f;

    const uint32_t aoff = (uint32_t)((wm * 64 + g) * 80 + t4 * 4);
    const uint32_t boff = (uint32_t)((wn * 32 + g) * 80 + t4 * 4);

    gemm_mainloop<512>(Ag, Bg, sb, tid, acc, aoff, boff);

    // -------------------- attention epilogue (two 64-row halves) ------------
    float* tile = (float*)smem;                         // [64][132]
    float* s_sq0 = (float*)(smem + 33792);              // [128]
    float* s_a0  = s_sq0 + 128;
    float* s_sq1 = s_a0 + 128;
    float* s_m1  = s_sq1 + 128;

    __syncthreads();   // mainloop smem dead
    if (tid < 128) {
        int i = tid;
        s_sq0[i] = g_sq0[b * SS + mt * 128 + i];
        s_a0[i]  = 2.f * m0_[b * SS + mt * 128 + i];
        s_sq1[i] = g_sq1[b * SS + nt * 128 + i];
        s_m1[i]  = m1_[b * SS + nt * 128 + i];
    }

    float* Aout  = g_A  + (size_t)b * SS * SS;
    float* Atout = g_At + (size_t)b * SS * SS;

    #pragma unroll 1
    for (int h = 0; h < 2; h++) {
        __syncthreads();
        if (wm == h) {
            #pragma unroll
            for (int mf = 0; mf < 4; mf++) {
                int lr = mf * 16 + g;
                #pragma unroll
                for (int nf = 0; nf < 4; nf++) {
                    int col = wn * 32 + nf * 8 + 2 * t4;
                    *(float2*)&tile[lr * 132 + col] =
                        make_float2(acc[mf][nf][0], acc[mf][nf][1]);
                    *(float2*)&tile[(lr + 8) * 132 + col] =
                        make_float2(acc[mf][nf][2], acc[mf][nf][3]);
                }
            }
        }
        __syncthreads();

        #pragma unroll
        for (int it = 0; it < 8; it++) {
            int lin = it * 1024 + tid * 4;
            int row = lin >> 7, col = lin & 127;
            int grow = h * 64 + row;
            float s0v = s_sq0[grow], a0v = s_a0[grow];
            float4 cr = *(float4*)&tile[row * 132 + col];
            float d2, v0, v1, v2, v3;
            d2 = fmaxf(s0v + s_sq1[col]     - a0v * s_m1[col]     * cr.x, 0.f);
            v0 = rtf32(1.f / (1.f + sqrtf(d2)));
            d2 = fmaxf(s0v + s_sq1[col + 1] - a0v * s_m1[col + 1] * cr.y, 0.f);
            v1 = rtf32(1.f / (1.f + sqrtf(d2)));
            d2 = fmaxf(s0v + s_sq1[col + 2] - a0v * s_m1[col + 2] * cr.z, 0.f);
            v2 = rtf32(1.f / (1.f + sqrtf(d2)));
            d2 = fmaxf(s0v + s_sq1[col + 3] - a0v * s_m1[col + 3] * cr.w, 0.f);
            v3 = rtf32(1.f / (1.f + sqrtf(d2)));
            *(float4*)&Aout[(size_t)(mt * 128 + grow) * SS + nt * 128 + col] =
                make_float4(v0, v1, v2, v3);
        }

        #pragma unroll
        for (int it = 0; it < 8; it++) {
            int pair = it * 256 + tid;
            int col = pair >> 4, rg = pair & 15;
            int r0 = rg * 4;
            float s1v = s_sq1[col], m1v = s_m1[col];
            float v[4];
            #pragma unroll
            for (int q = 0; q < 4; q++) {
                int row = r0 + q, grow = h * 64 + row;
                float cr = tile[row * 132 + col];
                float d2 = fmaxf(s_sq0[grow] + s1v - s_a0[grow] * m1v * cr, 0.f);
                v[q] = rtf32(1.f / (1.f + sqrtf(d2)));
            }
            *(float4*)&Atout[(size_t)(nt * 128 + col) * SS + mt * 128 + h * 64 + r0] =
                make_float4(v[0], v[1], v[2], v[3]);
        }
    }
}

// ---------------------------------------------------------------------------
// GEMM B (both aggregations in ONE launch).  blockIdx.y: 0,1 -> F0a (At@W0t),
// 2,3 -> F1a (A@W1t).  K=256.
// ---------------------------------------------------------------------------
__global__ __launch_bounds__(256, 2) void gemm_aggr(void)
{
    extern __shared__ char smem[];
    const int tid = threadIdx.x;
    const int wid = tid >> 5, lane = tid & 31;
    const int g = lane >> 2, t4 = lane & 3;
    const int wm = wid & 1, wn = wid >> 1;
    const int b = blockIdx.z, nt = blockIdx.x;
    const int sel = blockIdx.y >> 1;          // 0: F0a, 1: F1a
    const int mt  = blockIdx.y & 1;

    uint32_t sb = smem_u32(smem);
    const float* Ag = (sel ? g_A : g_At) + (size_t)b * SS * SS + (size_t)mt * 128 * SS;
    const float* Bg = (sel ? g_W1t : g_W0t) + (size_t)nt * 128 * SS;

    float acc[4][4][4];
    #pragma unroll
    for (int i = 0; i < 4; i++)
        #pragma unroll
        for (int j = 0; j < 4; j++)
            #pragma unroll
            for (int r = 0; r < 4; r++) acc[i][j][r] = 0.f;

    const uint32_t aoff = (uint32_t)((wm * 64 + g) * 80 + t4 * 4);
    const uint32_t boff = (uint32_t)((wn * 32 + g) * 80 + t4 * 4);

    gemm_mainloop<256>(Ag, Bg, sb, tid, acc, aoff, boff);

    float* O = (sel ? g_F1a : g_F0a) + (size_t)b * SS * DD;
    #pragma unroll
    for (int mf = 0; mf < 4; mf++) {
        int m = mt * 128 + wm * 64 + mf * 16 + g;
        #pragma unroll
        for (int nf = 0; nf < 4; nf++) {
            int col = nt * 128 + wn * 32 + nf * 8 + 2 * t4;
            *(float2*)&O[(size_t)m * DD + col] =
                make_float2(acc[mf][nf][0], acc[mf][nf][1]);
            *(float2*)&O[(size_t)(m + 8) * DD + col] =
                make_float2(acc[mf][nf][2], acc[mf][nf][3]);
        }
    }
}

// ---------------------------------------------------------------------------
// Conv (2ch, h=3, pad 2) + bias + tanh + avgpool(3), 8-row segments per thread
// ---------------------------------------------------------------------------
__device__ __forceinline__ float fast_tanh(float x)
{
    float e = __expf(2.f * x);
    return 1.f - __fdividef(2.f, 1.f + e);
}

__global__ __launch_bounds__(256) void conv_kernel(
    const float* __restrict__ F0r, const float* __restrict__ F1r,
    const float* __restrict__ m0, const float* __restrict__ m1,
    const float* __restrict__ conv_w, const float* __restrict__ conv_b,
    float* __restrict__ out)
{
    const int p = blockIdx.z & 1;
    const int b = blockIdx.z >> 1;
    const float* F  = p ? F1r : F0r;
    const float* mk = p ? m1 : m0;
    const float* Fa = p ? g_F1a : g_F0a;
    float* o = out + ((size_t)p * BB + b) * SS * DD;

    const int s0 = blockIdx.y * 8;
    const int d  = blockIdx.x * 256 + threadIdx.x;

    float w0[3], w1[3];
    #pragma unroll
    for (int h = 0; h < 3; h++) { w0[h] = conv_w[h]; w1[h] = conv_w[3 + h]; }
    const float cb = conv_b[0];

    float xf[12], xa[12];
    #pragma unroll
    for (int u = 0; u < 12; u++) {
        int t = s0 - 2 + u;
        bool in = (t >= 0) && (t < SS);
        if (in) {
            float mv = mk[b * SS + t];
            xf[u] = F [((size_t)b * SS + t) * DD + d] * mv;
            xa[u] = Fa[((size_t)b * SS + t) * DD + d];
        } else { xf[u] = 0.f; xa[u] = 0.f; }
    }

    float y[10];
    #pragma unroll
    for (int u = 0; u < 10; u++) {
        float acc = cb;
        #pragma unroll
        for (int h = 0; h < 3; h++)
            acc += w0[h] * xf[u + h] + w1[h] * xa[u + h];
        y[u] = fast_tanh(acc);
    }
    #pragma unroll
    for (int q = 0; q < 8; q++)
        o[(size_t)(s0 + q) * DD + d] = (y[q] + y[q + 1] + y[q + 2]) * (1.f / 3.f);
}

// ---------------------------------------------------------------------------
// Launch
// ---------------------------------------------------------------------------
extern "C" void kernel_launch(void* const* d_in, const int* in_sizes, int n_in,
                              void* d_out, int out_size)
{
    const float* F0r    = (const float*)d_in[0];
    const float* F1r    = (const float*)d_in[1];
    const float* m0     = (const float*)d_in[2];
    const float* m1     = (const float*)d_in[3];
    const float* W0     = (const float*)d_in[4];
    const float* W1     = (const float*)d_in[5];
    const float* conv_w = (const float*)d_in[6];
    const float* conv_b = (const float*)d_in[7];
    float* out = (float*)d_out;

    static int attr_done = 0;
    if (!attr_done) {
        cudaFuncSetAttribute(gemm_attn, cudaFuncAttributeMaxDynamicSharedMemorySize, GEMM_SMEM);
        cudaFuncSetAttribute(gemm_aggr, cudaFuncAttributeMaxDynamicSharedMemorySize, GEMM_SMEM);
        attr_done = 1;
    }

    sqnorm_kernel<<<BB * SS, 128>>>(F0r, F1r, m0, m1);
    wtrans_kernel<<<dim3(16, 8, 2), dim3(32, 8)>>>(W0, W1);

    gemm_attn<<<dim3(2, 2, BB), 256, GEMM_SMEM>>>(F0r, F1r, m0, m1);
    gemm_aggr<<<dim3(4, 4, BB), 256, GEMM_SMEM>>>();

    conv_kernel<<<dim3(2, 32, 2 * BB), 256>>>(F0r, F1r, m0, m1, conv_w, conv_b, out);
}